// round 17
// baseline (speedup 1.0000x reference)
#include <cuda_runtime.h>
#include <math.h>

// ---------------- Problem constants ----------------
#define BS      8192
#define NL      512
#define ML      32
#define DP      128     // D_PATH
#define G3      384     // 3*D_PATH
#define DR      256     // D_READ
#define NO      3

// GRU kernel tiling (R4/R13 configuration - measured fastest)
#define SPT     7
#define BT      28
#define NCHUNK  293
#define GRU_BLOCKS 148
#define GRU_THREADS 256
#define NPART   (GRU_BLOCKS * 4)

// ---------------- Device scratch ----------------
__device__ float g_flow[BS * DP];
__device__ float g_psum[NPART * DP];
__device__ float g_psumsq[NPART * DP];
__device__ float g_bnA[DP];
__device__ float g_bnB[DP];
__device__ int   g_maxbits;
__device__ int   g_order[BS];

// ---------------- packed f32x2 helpers ----------------
__device__ __forceinline__ void fma2(unsigned long long& d,
                                     unsigned long long a,
                                     unsigned long long b) {
    asm("fma.rn.f32x2 %0, %1, %2, %3;" : "=l"(d) : "l"(a), "l"(b), "l"(d));
}
__device__ __forceinline__ unsigned long long pk(float lo, float hi) {
    unsigned long long r;
    asm("mov.b64 %0, {%1, %2};" : "=l"(r)
        : "r"(__float_as_uint(lo)), "r"(__float_as_uint(hi)));
    return r;
}
__device__ __forceinline__ unsigned long long splat(float a) {
    unsigned long long r;
    asm("mov.b64 %0, {%1, %1};" : "=l"(r) : "r"(__float_as_uint(a)));
    return r;
}
__device__ __forceinline__ float upksum(unsigned long long v) {
    float lo = __uint_as_float((unsigned)(v & 0xffffffffull));
    float hi = __uint_as_float((unsigned)(v >> 32));
    return lo + hi;
}
__device__ __forceinline__ float upklo(unsigned long long v) {
    return __uint_as_float((unsigned)(v & 0xffffffffull));
}
__device__ __forceinline__ float upkhi(unsigned long long v) {
    return __uint_as_float((unsigned)(v >> 32));
}

__device__ __forceinline__ float tanhap(float x) {
    float y;
    asm("tanh.approx.f32 %0, %1;" : "=f"(y) : "f"(x));
    return y;
}
__device__ __forceinline__ float sigm(float x) {
    return 0.5f * tanhap(0.5f * x) + 0.5f;
}
__device__ __forceinline__ float seluf(float x) {
    const float sc = 1.0507009873554805f;
    const float al = 1.6732632423543772f;
    return x > 0.f ? sc * x : sc * al * (expf(x) - 1.f);
}

// ---------------- cp.async helpers ----------------
__device__ __forceinline__ unsigned smaddr(const void* p) {
    unsigned r;
    asm("{ .reg .u64 t; cvta.to.shared.u64 t, %1; cvt.u32.u64 %0, t; }"
        : "=r"(r) : "l"(p));
    return r;
}
__device__ __forceinline__ void cpasync16(unsigned s, const void* g) {
    asm volatile("cp.async.ca.shared.global [%0], [%1], 16;" :: "r"(s), "l"(g));
}
__device__ __forceinline__ void cpcommit() {
    asm volatile("cp.async.commit_group;");
}
__device__ __forceinline__ void cpwait1() {
    asm volatile("cp.async.wait_group 1;" ::: "memory");
}
__device__ __forceinline__ void cpwait0() {
    asm volatile("cp.async.wait_group 0;" ::: "memory");
}

// ---------------- fused max + hist/scan/scatter ----------------
__global__ void k_maxprep(const float* __restrict__ capa,
                          const int* __restrict__ hop) {
    if (blockIdx.x < 256) {
        int i = blockIdx.x * blockDim.x + threadIdx.x;
        int stride = 256 * 256;
        const float4* c4 = (const float4*)capa;
        float m = 0.f;
        for (int q = i; q < (BS * NL) / 4; q += stride) {
            float4 v = c4[q];
            m = fmaxf(m, fmaxf(fmaxf(v.x, v.y), fmaxf(v.z, v.w)));
        }
#pragma unroll
        for (int off = 16; off > 0; off >>= 1)
            m = fmaxf(m, __shfl_down_sync(0xffffffffu, m, off));
        if ((threadIdx.x & 31) == 0) atomicMax(&g_maxbits, __float_as_int(m));
    } else {
        __shared__ int cnt[33];
        __shared__ int off[33];
        int t = threadIdx.x;
        if (t < 33) cnt[t] = 0;
        __syncthreads();
        for (int b = t; b < BS; b += 256) atomicAdd(&cnt[hop[b]], 1);
        __syncthreads();
        if (t == 0) {
            int acc = 0;
            for (int h = 32; h >= 1; h--) { off[h] = acc; acc += cnt[h]; }
        }
        __syncthreads();
        for (int b = t; b < BS; b += 256) {
            int pos = atomicAdd(&off[hop[b]], 1);
            g_order[pos] = b;
        }
    }
}

// ---------------- GRU (R13, measured fastest) ----------------
__global__ void __launch_bounds__(GRU_THREADS, 1)
k_gru(const float* __restrict__ demand,
      const float* __restrict__ avail,
      const float* __restrict__ capa,
      const float* __restrict__ loss,
      const int*   __restrict__ path,
      const int*   __restrict__ hop,
      const float* __restrict__ w_ih,
      const float* __restrict__ w_hh,
      const float* __restrict__ b_ih,
      const float* __restrict__ b_hh)
{
    extern __shared__ float sm[];
    float* wsh = sm;
    float* hbuf0 = sm + 49152;
    float* hbuf1 = hbuf0 + BT * DP;
    float* xbuf0 = hbuf1 + BT * DP;
    float* xbuf1 = xbuf0 + BT * 4;
    int*   sb    = (int*)(xbuf1 + BT * 4);
    int*   shop  = sb + BT;
    int*   smaxh = shop + BT;

    const int tid = threadIdx.x;
    const int jt = tid & 63;
    const int sg = tid >> 6;

    const float4* w4g = (const float4*)w_hh;
    for (int q = tid; q < G3 * 32; q += GRU_THREADS) {
        int j = q >> 5, k4 = q & 31;
        float4 v = __ldg(w4g + q);
        ((float4*)wsh)[(j << 5) + (k4 ^ (j & 31))] = v;
    }

    const float maxc = __int_as_float(g_maxbits);
    const float inv_maxc = 1.f / maxc;

    float wih[6][4], bihv[6], bhhv[6];
    int wbase4[6], jx[6];
#pragma unroll
    for (int dd = 0; dd < 2; dd++) {
#pragma unroll
        for (int g = 0; g < 3; g++) {
            int i = dd * 3 + g;
            int j = g * 128 + jt + dd * 64;
#pragma unroll
            for (int c = 0; c < 4; c++) wih[i][c] = __ldg(w_ih + j * 32 + 28 + c);
            bihv[i] = __ldg(b_ih + j);
            bhhv[i] = __ldg(b_hh + j);
            wbase4[i] = j << 5;
            jx[i] = j & 31;
        }
    }

    float bns[2] = {0.f, 0.f}, bnq[2] = {0.f, 0.f};

    for (int cidx = 0; cidx < 2; cidx++) {
        int chunk = (cidx == 0) ? (int)blockIdx.x : (NCHUNK - 1 - (int)blockIdx.x);
        if (cidx == 1 && chunk < GRU_BLOCKS) break;
        int base = chunk * BT;
        int cnt = min(BT, BS - base);

        if (tid == 0) *smaxh = 0;
        __syncthreads();
        int myb = -1, myhop = 0;
        if (tid < BT) {
            if (tid < cnt) { myb = g_order[base + tid]; myhop = hop[myb]; }
            sb[tid] = myb; shop[tid] = myhop;
            atomicMax(smaxh, myhop);
        }
        for (int q = tid; q < BT * DP; q += GRU_THREADS) hbuf0[q] = 0.f;
        __syncthreads();
        if (tid < cnt) hbuf0[tid * DP + (DP - 1)] = demand[myb] * inv_maxc;
        int maxh = *smaxh;

        float f0 = 0.f, f1 = 0.f, f2 = 0.f, f3 = 0.f;
        if (tid < cnt && myhop > 0) {
            int l = path[myb * ML + 0];
            float a = avail[myb * NL + l];
            float c = capa[myb * NL + l];
            float lo = loss[myb * NL + l];
            xbuf0[tid * 4 + 0] = a * inv_maxc;
            xbuf0[tid * 4 + 1] = c * inv_maxc;
            xbuf0[tid * 4 + 2] = a / c;
            xbuf0[tid * 4 + 3] = lo;
        }
        if (tid < cnt && myhop > 1) {
            int l = path[myb * ML + 1];
            float a = avail[myb * NL + l];
            float c = capa[myb * NL + l];
            f0 = a * inv_maxc; f1 = c * inv_maxc;
            f2 = a / c; f3 = loss[myb * NL + l];
        }
        __syncthreads();

        for (int t = 0; t < maxh; t++) {
            float* hR = (t & 1) ? hbuf1 : hbuf0;
            float* hW = (t & 1) ? hbuf0 : hbuf1;
            float* xR = (t & 1) ? xbuf1 : xbuf0;
            float* xW = (t & 1) ? xbuf0 : xbuf1;

            if (tid < cnt && t + 1 < myhop) {
                xW[tid * 4 + 0] = f0; xW[tid * 4 + 1] = f1;
                xW[tid * 4 + 2] = f2; xW[tid * 4 + 3] = f3;
            }
            if (tid < cnt && t + 2 < myhop) {
                int l = path[myb * ML + t + 2];
                float a = avail[myb * NL + l];
                float c = capa[myb * NL + l];
                f0 = a * inv_maxc; f1 = c * inv_maxc;
                f2 = a / c; f3 = loss[myb * NL + l];
            }

            unsigned long long acc2[6][SPT];
#pragma unroll
            for (int i = 0; i < 6; i++)
#pragma unroll
                for (int s = 0; s < SPT; s++) acc2[i][s] = 0ull;

            const ulonglong2* hsp = (const ulonglong2*)hR;
            const ulonglong2* wsp = (const ulonglong2*)wsh;
            const int sbase = sg * SPT * 32;
#pragma unroll 2
            for (int k4 = 0; k4 < 32; k4++) {
                ulonglong2 wv[6];
#pragma unroll
                for (int i = 0; i < 6; i++)
                    wv[i] = wsp[wbase4[i] + (k4 ^ jx[i])];
#pragma unroll
                for (int ss = 0; ss < SPT; ss++) {
                    ulonglong2 hv = hsp[sbase + ss * 32 + k4];
#pragma unroll
                    for (int i = 0; i < 6; i++) {
                        fma2(acc2[i][ss], wv[i].x, hv.x);
                        fma2(acc2[i][ss], wv[i].y, hv.y);
                    }
                }
            }

#pragma unroll
            for (int ss = 0; ss < SPT; ss++) {
                int s = sg * SPT + ss;
                int hp = shop[s];
                if (t < hp) {
                    float x0 = xR[s * 4 + 0], x1 = xR[s * 4 + 1];
                    float x2 = xR[s * 4 + 2], x3 = xR[s * 4 + 3];
#pragma unroll
                    for (int dd = 0; dd < 2; dd++) {
                        int d = jt + dd * 64;
                        int ir = dd * 3 + 0, iz = dd * 3 + 1, in_ = dd * 3 + 2;
                        float ar = upksum(acc2[ir][ss]);
                        float az = upksum(acc2[iz][ss]);
                        float an = upksum(acc2[in_][ss]);
                        float gr = bihv[ir] + wih[ir][0] * x0 + wih[ir][1] * x1
                                 + wih[ir][2] * x2 + wih[ir][3] * x3 + ar + bhhv[ir];
                        float gz = bihv[iz] + wih[iz][0] * x0 + wih[iz][1] * x1
                                 + wih[iz][2] * x2 + wih[iz][3] * x3 + az + bhhv[iz];
                        float gni = bihv[in_] + wih[in_][0] * x0 + wih[in_][1] * x1
                                  + wih[in_][2] * x2 + wih[in_][3] * x3;
                        float gnh = an + bhhv[in_];
                        float r = sigm(gr);
                        float z = sigm(gz);
                        float n = tanhap(gni + r * gnh);
                        float hold = hR[s * DP + d];
                        float hnew = (1.f - z) * n + z * hold;
                        hW[s * DP + d] = hnew;
                        if (t == hp - 1) {
                            g_flow[sb[s] * DP + d] = hnew;
                            bns[dd] += hnew;
                            bnq[dd] += hnew * hnew;
                        }
                    }
                }
            }
            __syncthreads();
        }
    }

    int slot = ((int)blockIdx.x * 4 + sg) * DP;
    g_psum[slot + jt]      = bns[0];
    g_psum[slot + jt + 64] = bns[1];
    g_psumsq[slot + jt]      = bnq[0];
    g_psumsq[slot + jt + 64] = bnq[1];
}

// ---------------- BN final ----------------
__global__ void k_bnfinal(const float* __restrict__ gamma, const float* __restrict__ beta) {
    __shared__ float ssum[8 * DP];
    __shared__ float ssq[8 * DP];
    int tid = threadIdx.x;
    int d = tid & 127;
    int seg = tid >> 7;
    float s = 0.f, s2 = 0.f;
    for (int blk = seg; blk < NPART; blk += 8) {
        s += g_psum[blk * DP + d];
        s2 += g_psumsq[blk * DP + d];
    }
    ssum[seg * DP + d] = s;
    ssq[seg * DP + d] = s2;
    __syncthreads();
    if (tid < DP) {
        float ts = 0.f, ts2 = 0.f;
#pragma unroll
        for (int g = 0; g < 8; g++) {
            ts += ssum[g * DP + tid];
            ts2 += ssq[g * DP + tid];
        }
        float mean = ts * (1.f / BS);
        float var = ts2 * (1.f / BS) - mean * mean;
        float rstd = rsqrtf(var + 1e-5f);
        float A = rstd * gamma[tid];
        g_bnA[tid] = A;
        g_bnB[tid] = beta[tid] - mean * A;
    }
}

// ---------------- fused readout, 32x256 tile, 3 CTAs/SM, cp.async B ----------------
// smem: h1p 34816 | Bs ring 2x16384 | As(2048) union red(4096) => 71680 B
#define RD_SMEM (34816 + 32768 + 4096)
__global__ void __launch_bounds__(256, 3)
k_read(const float* __restrict__ rW1, const float* __restrict__ rb1,
       const float* __restrict__ rW2, const float* __restrict__ rb2,
       const float* __restrict__ rW3, const float* __restrict__ rb3,
       float* __restrict__ out) {
    extern __shared__ char smraw[];
    unsigned long long* h1p = (unsigned long long*)smraw;          // 256*17 ull
    float* Bs0 = (float*)(smraw + 34816);                          // 16*256 f
    float* Bs1 = (float*)(smraw + 34816 + 16384);                  // 16*256 f
    float* As  = (float*)(smraw + 34816 + 32768);                  // 16*32 f (phase 1)
    float* red = (float*)(smraw + 34816 + 32768);                  // 32*32 f (epilogue)

    int tid = threadIdx.x;
    int m0 = blockIdx.x * 32, u = blockIdx.y;
    int trow = tid >> 5, tcol = tid & 31;

    unsigned bs_sm[2] = { smaddr(Bs0), smaddr(Bs1) };
    float* bs_ptr[2] = { Bs0, Bs1 };

    // per-thread B staging coordinates (4 x 16B segments)
    int bk[4], bn4[4];
#pragma unroll
    for (int r = 0; r < 4; r++) {
        int idx = r * 256 + tid;
        bk[r] = idx >> 6;
        bn4[r] = (idx & 63) * 4;
    }

    unsigned long long acc2[2][8];
#pragma unroll
    for (int i = 0; i < 2; i++)
#pragma unroll
        for (int j = 0; j < 8; j++) acc2[i][j] = 0ull;

    const int am = tid >> 3, akq = tid & 7;   // A staging: 32 rows x 16 k, float2 each

    // ================= phase 1: h1 = selu(BN(flow) @ rW1 + rb1) =================
    const float* B1 = rW1 + u * DP * DR;
#pragma unroll
    for (int r = 0; r < 4; r++)
        cpasync16(bs_sm[0] + (bk[r] * 256 + bn4[r]) * 4, B1 + bk[r] * DR + bn4[r]);
    cpcommit();
    float2 areg = *(const float2*)(g_flow + (m0 + am) * DP + akq * 2);

#pragma unroll 1
    for (int i = 0; i < 8; i++) {
        if (i < 7) {   // stage B chunk i+1 into the other buffer
            int k0n = (i + 1) * 16;
            unsigned dst = bs_sm[(i + 1) & 1];
#pragma unroll
            for (int r = 0; r < 4; r++)
                cpasync16(dst + (bk[r] * 256 + bn4[r]) * 4,
                          B1 + (k0n + bk[r]) * DR + bn4[r]);
            cpcommit();
        }
        {   // STS A chunk i with BN
            int kb = i * 16 + akq * 2;
            As[(akq * 2 + 0) * 32 + am] = areg.x * g_bnA[kb + 0] + g_bnB[kb + 0];
            As[(akq * 2 + 1) * 32 + am] = areg.y * g_bnA[kb + 1] + g_bnB[kb + 1];
        }
        if (i < 7)
            areg = *(const float2*)(g_flow + (m0 + am) * DP + (i + 1) * 16 + akq * 2);
        if (i < 7) cpwait1(); else cpwait0();
        __syncthreads();

        const float* Bc = bs_ptr[i & 1];
#pragma unroll
        for (int kk = 0; kk < 16; kk++) {
            ulonglong2 a01 = *(const ulonglong2*)&As[kk * 32 + trow * 4];
            unsigned long long ap[2] = {a01.x, a01.y};
#pragma unroll
            for (int jj = 0; jj < 4; jj++) {
                float2 bv = *(const float2*)&Bc[kk * 256 + tcol * 2 + 64 * jj];
                unsigned long long bx = splat(bv.x), by = splat(bv.y);
#pragma unroll
                for (int mp = 0; mp < 2; mp++) {
                    fma2(acc2[mp][jj * 2 + 0], ap[mp], bx);
                    fma2(acc2[mp][jj * 2 + 1], ap[mp], by);
                }
            }
        }
        __syncthreads();
    }
    // epilogue: selu + pack into h1p (stride 17 ull per col)
#pragma unroll
    for (int mp = 0; mp < 2; mp++) {
#pragma unroll
        for (int j = 0; j < 8; j++) {
            int c = tcol * 2 + 64 * (j >> 1) + (j & 1);
            float b = rb1[u * DR + c];
            float lo = seluf(upklo(acc2[mp][j]) + b);
            float hi = seluf(upkhi(acc2[mp][j]) + b);
            h1p[c * 17 + trow * 2 + mp] = pk(lo, hi);
        }
    }
    __syncthreads();

    // ================= phase 2: h2 = selu(h1 @ rW2 + rb2); y = h2 . rW3 =================
    const float* B2 = rW2 + u * DR * DR;

#pragma unroll
    for (int i = 0; i < 2; i++)
#pragma unroll
        for (int j = 0; j < 8; j++) acc2[i][j] = 0ull;

#pragma unroll
    for (int r = 0; r < 4; r++)
        cpasync16(bs_sm[0] + (bk[r] * 256 + bn4[r]) * 4, B2 + bk[r] * DR + bn4[r]);
    cpcommit();

#pragma unroll 1
    for (int i = 0; i < 16; i++) {
        if (i < 15) {
            int k0n = (i + 1) * 16;
            unsigned dst = bs_sm[(i + 1) & 1];
#pragma unroll
            for (int r = 0; r < 4; r++)
                cpasync16(dst + (bk[r] * 256 + bn4[r]) * 4,
                          B2 + (k0n + bk[r]) * DR + bn4[r]);
            cpcommit();
        }
        if (i < 15) cpwait1(); else cpwait0();
        __syncthreads();

        const float* Bc = bs_ptr[i & 1];
        const int kgb = i * 16;
#pragma unroll
        for (int kk = 0; kk < 16; kk++) {
            int kg = kgb + kk;
            // scalar 64-bit broadcast loads (8B-aligned at any kg)
            unsigned long long ap[2];
            ap[0] = h1p[kg * 17 + trow * 2 + 0];
            ap[1] = h1p[kg * 17 + trow * 2 + 1];
#pragma unroll
            for (int jj = 0; jj < 4; jj++) {
                float2 bv = *(const float2*)&Bc[kk * 256 + tcol * 2 + 64 * jj];
                unsigned long long bx = splat(bv.x), by = splat(bv.y);
#pragma unroll
                for (int mp = 0; mp < 2; mp++) {
                    fma2(acc2[mp][jj * 2 + 0], ap[mp], bx);
                    fma2(acc2[mp][jj * 2 + 1], ap[mp], by);
                }
            }
        }
        __syncthreads();
    }
    // epilogue: selu + dot w3 + block reduce
    float w3v[8];
#pragma unroll
    for (int j = 0; j < 8; j++)
        w3v[j] = __ldg(rW3 + u * DR + tcol * 2 + 64 * (j >> 1) + (j & 1));
#pragma unroll
    for (int mp = 0; mp < 2; mp++) {
#pragma unroll
        for (int e = 0; e < 2; e++) {
            int i = trow * 4 + mp * 2 + e;
            float p = 0.f;
#pragma unroll
            for (int j = 0; j < 8; j++) {
                int c = tcol * 2 + 64 * (j >> 1) + (j & 1);
                float v = e ? upkhi(acc2[mp][j]) : upklo(acc2[mp][j]);
                float h2 = seluf(v + rb2[u * DR + c]);
                p += h2 * w3v[j];
            }
            red[i * 32 + tcol] = p;
        }
    }
    __syncthreads();
    if (tid < 32) {
        float y = rb3[u];
#pragma unroll
        for (int c = 0; c < 32; c++) y += red[tid * 32 + c];
        out[(m0 + tid) * NO + u] = y;
    }
}

// ---------------- launcher ----------------
extern "C" void kernel_launch(void* const* d_in, const int* in_sizes, int n_in,
                              void* d_out, int out_size) {
    const float* demand = (const float*)d_in[0];
    const float* avail  = (const float*)d_in[1];
    const float* capa   = (const float*)d_in[2];
    const float* loss   = (const float*)d_in[3];
    const int*   path   = (const int*)d_in[4];
    const int*   hop    = (const int*)d_in[5];
    const float* w_ih   = (const float*)d_in[6];
    const float* w_hh   = (const float*)d_in[7];
    const float* b_ih   = (const float*)d_in[8];
    const float* b_hh   = (const float*)d_in[9];
    const float* gamma  = (const float*)d_in[10];
    const float* beta   = (const float*)d_in[11];
    const float* rW1    = (const float*)d_in[12];
    const float* rb1    = (const float*)d_in[13];
    const float* rW2    = (const float*)d_in[14];
    const float* rb2    = (const float*)d_in[15];
    const float* rW3    = (const float*)d_in[16];
    const float* rb3    = (const float*)d_in[17];
    float* out = (float*)d_out;

    const int GRU_SMEM = (49152 + 2 * BT * DP + 2 * BT * 4) * 4
                       + (2 * BT + 1) * 4 + 256;
    cudaFuncSetAttribute(k_gru, cudaFuncAttributeMaxDynamicSharedMemorySize, GRU_SMEM);
    cudaFuncSetAttribute(k_read, cudaFuncAttributeMaxDynamicSharedMemorySize, RD_SMEM);

    k_maxprep<<<257, 256>>>(capa, hop);                    // idx 0
    k_gru<<<GRU_BLOCKS, GRU_THREADS, GRU_SMEM>>>(          // idx 1
        demand, avail, capa, loss, path, hop, w_ih, w_hh, b_ih, b_hh);
    k_bnfinal<<<1, 1024>>>(gamma, beta);                   // idx 2
    {
        dim3 gr(BS / 32, NO);
        k_read<<<gr, 256, RD_SMEM>>>(rW1, rb1, rW2, rb2, rW3, rb3, out);  // idx 3
    }
}